// round 13
// baseline (speedup 1.0000x reference)
#include <cuda_runtime.h>
#include <cstdint>

#define NN 200000
#define CC 256
#define MM 50000
#define VCD 48   // 16 vector channels * 3 spatial dims
#define NB 98    // scan blocks: ceil(MM / 512)

// Scratch (device globals; no allocation allowed in kernel_launch)
__device__ float g_s_mean[(size_t)MM * CC];   // 51.2 MB
__device__ float g_v_mean[(size_t)MM * VCD];  // 9.6 MB
__device__ int   g_hist[MM];
__device__ int   g_bsum[NB];
__device__ int   g_off[MM + 1];
__device__ int   g_fill[MM];
__device__ int   g_perm[NN];
__device__ int   g_seg_is64;

// ============================ helpers ======================================
__device__ __forceinline__ uint32_t smem_u32(const void* p) {
    uint32_t a;
    asm("{ .reg .u64 t; cvta.to.shared.u64 t, %1; cvt.u32.u64 %0, t; }"
        : "=r"(a) : "l"(p));
    return a;
}
__device__ __forceinline__ float to_tf32(float x) {
    float r;
    asm("cvt.rna.tf32.f32 %0, %1;" : "=f"(r) : "f"(x));
    return r;
}
__device__ __forceinline__ void ldsm_x4(uint32_t* r, uint32_t addr) {
    asm volatile("ldmatrix.sync.aligned.m8n8.x4.shared.b16 {%0,%1,%2,%3}, [%4];"
        : "=r"(r[0]), "=r"(r[1]), "=r"(r[2]), "=r"(r[3]) : "r"(addr));
}
__device__ __forceinline__ void ldsm_x2(uint32_t* r, uint32_t addr) {
    asm volatile("ldmatrix.sync.aligned.m8n8.x2.shared.b16 {%0,%1}, [%2];"
        : "=r"(r[0]), "=r"(r[1]) : "r"(addr));
}
__device__ __forceinline__ void mma_tf32(float* c, const uint32_t* a, const uint32_t* b) {
    asm volatile(
        "mma.sync.aligned.m16n8k8.row.col.f32.tf32.tf32.f32 "
        "{%0,%1,%2,%3}, {%4,%5,%6,%7}, {%8,%9}, {%0,%1,%2,%3};"
        : "+f"(c[0]), "+f"(c[1]), "+f"(c[2]), "+f"(c[3])
        : "r"(a[0]), "r"(a[1]), "r"(a[2]), "r"(a[3]), "r"(b[0]), "r"(b[1]));
}
__device__ __forceinline__ void cp_async16(uint32_t saddr, const void* gaddr,
                                           uint32_t src_size) {
    asm volatile("cp.async.ca.shared.global [%0], [%1], 16, %2;"
                 :: "r"(saddr), "l"(gaddr), "r"(src_size) : "memory");
}
__device__ __forceinline__ void add4(float4& a, const float4 b) {
    a.x += b.x; a.y += b.y; a.z += b.z; a.w += b.w;
}

// ---------------------------------------------------------------------------
// Probe the segment-index buffer's dtype (int64 vs int32).
// ---------------------------------------------------------------------------
__global__ void probe_seg_kernel(const int* __restrict__ seg32) {
    __shared__ int any_nonzero;
    if (threadIdx.x == 0) any_nonzero = 0;
    __syncthreads();
    for (int i = threadIdx.x; i < 1024; i += blockDim.x)
        if (seg32[2 * i + 1] != 0) any_nonzero = 1;
    __syncthreads();
    if (threadIdx.x == 0) g_seg_is64 = (any_nonzero == 0) ? 1 : 0;
}
__device__ __forceinline__ int load_seg(const void* seg, int n, int is64) {
    if (is64) return (int)((const long long*)seg)[n];
    return ((const int*)seg)[n];
}

// ======================= counting sort build ===============================
__global__ void zero_hist_kernel() {
    int i = blockIdx.x * blockDim.x + threadIdx.x;
    if (i < MM) g_hist[i] = 0;
}

__global__ void hist_kernel(const void* __restrict__ seg) {
    int n = blockIdx.x * blockDim.x + threadIdx.x;
    if (n >= NN) return;
    int m = load_seg(seg, n, g_seg_is64);
    if ((unsigned)m < MM) atomicAdd(&g_hist[m], 1);
}

// scan_a: per-block (512 elems) sum
__global__ void scan_a_kernel() {
    __shared__ int red[256];
    int b = blockIdx.x, t = threadIdx.x;
    int i0 = b * 512 + t, i1 = i0 + 256;
    int c = (i0 < MM ? g_hist[i0] : 0) + (i1 < MM ? g_hist[i1] : 0);
    red[t] = c;
    __syncthreads();
    for (int s = 128; s > 0; s >>= 1) {
        if (t < s) red[t] += red[t + s];
        __syncthreads();
    }
    if (t == 0) g_bsum[b] = red[0];
}

// scan_c: per-block exclusive scan over its 512 counts. The 98-block-sum
// prefix is computed LOCALLY from raw g_bsum (scan_b eliminated): thread 0
// sums bsum[0..b-1]; block 0 also writes the grand total to g_off[MM].
__global__ void scan_c_kernel() {
    __shared__ int buf0[256], buf1[256];
    __shared__ int bs_sh[NB];
    __shared__ int base_blk;
    int b = blockIdx.x, t = threadIdx.x;
    for (int i = t; i < NB; i += blockDim.x) bs_sh[i] = g_bsum[i];

    int i0 = b * 512 + 2 * t, i1 = i0 + 1;
    int c0 = (i0 < MM) ? g_hist[i0] : 0;
    int c1 = (i1 < MM) ? g_hist[i1] : 0;
    int psum = c0 + c1;
    buf0[t] = psum;
    __syncthreads();

    if (t == 0) {
        int run = 0;
        for (int i = 0; i < b; i++) run += bs_sh[i];
        base_blk = run;
        if (b == 0) {
            int tot = 0;
            for (int i = 0; i < NB; i++) tot += bs_sh[i];
            g_off[MM] = tot;
        }
    }

    int* src = buf0; int* dst = buf1;
#pragma unroll
    for (int off = 1; off < 256; off <<= 1) {
        int val = src[t];
        if (t >= off) val += src[t - off];
        dst[t] = val;
        __syncthreads();
        int* tmp = src; src = dst; dst = tmp;
    }
    int excl = src[t] - psum;
    int base = base_blk + excl;
    if (i0 < MM) { g_off[i0] = base;      g_fill[i0] = base; }
    if (i1 < MM) { g_off[i1] = base + c0; g_fill[i1] = base + c0; }
}

__global__ void perm_kernel(const void* __restrict__ seg) {
    int n = blockIdx.x * blockDim.x + threadIdx.x;
    if (n >= NN) return;
    int m = load_seg(seg, n, g_seg_is64);
    if ((unsigned)m >= MM) return;
    int pos = atomicAdd(&g_fill[m], 1);
    g_perm[pos] = n;
}

// ---------------------------------------------------------------------------
// gather_mean (R9/R11 proven): one warp per motif, 2-node unroll.
// ---------------------------------------------------------------------------
__global__ void __launch_bounds__(256)
gather_mean_kernel(const float* __restrict__ s, const float* __restrict__ v) {
    int w = (blockIdx.x * blockDim.x + threadIdx.x) >> 5;
    if (w >= MM) return;
    int lane = threadIdx.x & 31;
    int beg = g_off[w], end = g_off[w + 1];

    float4 a0 = make_float4(0.f, 0.f, 0.f, 0.f), a1 = a0;
    float4 b0 = a0, b1 = a0;
    float4 va = a0, vb = a0;
    const float4* s4 = (const float4*)s;
    const float4* v4 = (const float4*)v;

    int i = beg;
    for (; i + 1 < end; i += 2) {
        int n0 = g_perm[i], n1 = g_perm[i + 1];
        add4(a0, s4[(size_t)n0 * 64 + lane * 2]);
        add4(b0, s4[(size_t)n1 * 64 + lane * 2]);
        add4(a1, s4[(size_t)n0 * 64 + lane * 2 + 1]);
        add4(b1, s4[(size_t)n1 * 64 + lane * 2 + 1]);
        if (lane < 12) {
            add4(va, v4[(size_t)n0 * 12 + lane]);
            add4(vb, v4[(size_t)n1 * 12 + lane]);
        }
    }
    if (i < end) {
        int n0 = g_perm[i];
        add4(a0, s4[(size_t)n0 * 64 + lane * 2]);
        add4(a1, s4[(size_t)n0 * 64 + lane * 2 + 1]);
        if (lane < 12) add4(va, v4[(size_t)n0 * 12 + lane]);
    }
    add4(a0, b0); add4(a1, b1); add4(va, vb);

    int cnt = end - beg;
    float inv = 1.0f / (float)(cnt > 0 ? cnt : 1);
    a0.x *= inv; a0.y *= inv; a0.z *= inv; a0.w *= inv;
    a1.x *= inv; a1.y *= inv; a1.z *= inv; a1.w *= inv;
    ((float4*)g_s_mean)[(size_t)w * 64 + lane * 2]     = a0;
    ((float4*)g_s_mean)[(size_t)w * 64 + lane * 2 + 1] = a1;
    if (lane < 12) {
        va.x *= inv; va.y *= inv; va.z *= inv; va.w *= inv;
        ((float4*)g_v_mean)[(size_t)w * 12 + lane] = va;
    }
}

// ---------------------------------------------------------------------------
// Single-pass tf32 mma.sync GEMM, cp.async double-buffered A and B (raw f32
// tiles), tf32 rounding post-ldmatrix. BM=128, BN=128, BK=32, occ=2.
// (R11 proven version, unchanged.)
// ---------------------------------------------------------------------------
#define SMO_BS   0
#define SMO_A    1024                 // 2 stages x 16KB
#define SMO_B    (1024 + 32768)       // 2 stages x 16KB
#define SMO_TOTAL (1024 + 65536)

__global__ void __launch_bounds__(256, 2)
gemm_s_mma(const float* __restrict__ Ws, const float* __restrict__ bs,
           float* __restrict__ out) {
    extern __shared__ char sm[];
    uint32_t sb = smem_u32(sm);
    int tid = threadIdx.x, wid = tid >> 5, lane = tid & 31;
    int wm = wid & 1, wn = wid >> 1;
    int m0 = blockIdx.y * 128, n0 = blockIdx.x * 128;

    float* bssh = (float*)(sm + SMO_BS);
    if (tid < 128) bssh[tid] = bs[n0 + tid];

    const float* gA[4]; const float* gB[4];
    uint32_t offAB[4]; uint32_t szA[4];
#pragma unroll
    for (int i = 0; i < 4; i++) {
        int f = tid + 256 * i;
        int row = f >> 3, q = f & 7;
        int gm = m0 + row;
        bool ok = (gm < MM);
        gA[i] = g_s_mean + (size_t)(ok ? gm : 0) * CC + q * 4;
        szA[i] = ok ? 16u : 0u;
        gB[i] = Ws + (size_t)(n0 + row) * CC + q * 4;
        offAB[i] = row * 128 + ((q ^ (row & 7)) << 4);
    }

    float acc[4][4][4];
#pragma unroll
    for (int a = 0; a < 4; a++)
#pragma unroll
        for (int b = 0; b < 4; b++)
#pragma unroll
            for (int c = 0; c < 4; c++) acc[a][b][c] = 0.f;

    int r8 = lane & 7;
    int halfA = (lane >> 3) & 1;
    int ksubA = lane >> 4;
    int ksubB = (lane >> 3) & 1;
    uint32_t aRowOff[4]; int aRsw[4];
#pragma unroll
    for (int mi = 0; mi < 4; mi++) {
        int row = wm * 64 + mi * 16 + halfA * 8 + r8;
        aRowOff[mi] = row * 128;
        aRsw[mi] = row & 7;
    }
    uint32_t bRowOff[4];
#pragma unroll
    for (int ni = 0; ni < 4; ni++)
        bRowOff[ni] = (wn * 32 + ni * 8 + r8) * 128;

#define LOAD_TILES(CH, ST)                                                        \
    {                                                                             \
        uint32_t ab = sb + SMO_A + (ST) * 16384;                                  \
        uint32_t bb = sb + SMO_B + (ST) * 16384;                                  \
        int kt = (CH) * 32;                                                       \
        _Pragma("unroll")                                                         \
        for (int i = 0; i < 4; i++) cp_async16(ab + offAB[i], gA[i] + kt, szA[i]);\
        _Pragma("unroll")                                                         \
        for (int i = 0; i < 4; i++) cp_async16(bb + offAB[i], gB[i] + kt, 16u);   \
        asm volatile("cp.async.commit_group;" ::: "memory");                      \
    }

    LOAD_TILES(0, 0)

    for (int ch = 0; ch < 8; ch++) {
        if (ch < 7) {
            LOAD_TILES(ch + 1, (ch + 1) & 1)
            asm volatile("cp.async.wait_group 1;" ::: "memory");
        } else {
            asm volatile("cp.async.wait_group 0;" ::: "memory");
        }
        __syncthreads();

        uint32_t ab = sb + SMO_A + (ch & 1) * 16384;
        uint32_t bb = sb + SMO_B + (ch & 1) * 16384;
#pragma unroll
        for (int ks = 0; ks < 4; ks++) {
            int ks2 = ks * 2;
            uint32_t bf[4][2];
#pragma unroll
            for (int ni = 0; ni < 4; ni++) {
                ldsm_x2(bf[ni], bb + bRowOff[ni] + (((ks2 + ksubB) ^ r8) << 4));
                bf[ni][0] = __float_as_uint(to_tf32(__uint_as_float(bf[ni][0])));
                bf[ni][1] = __float_as_uint(to_tf32(__uint_as_float(bf[ni][1])));
            }
#pragma unroll
            for (int mi = 0; mi < 4; mi++) {
                uint32_t ah[4];
                uint32_t ca = ((uint32_t)((ks2 + ksubA) ^ aRsw[mi])) << 4;
                ldsm_x4(ah, ab + aRowOff[mi] + ca);
                ah[0] = __float_as_uint(to_tf32(__uint_as_float(ah[0])));
                ah[1] = __float_as_uint(to_tf32(__uint_as_float(ah[1])));
                ah[2] = __float_as_uint(to_tf32(__uint_as_float(ah[2])));
                ah[3] = __float_as_uint(to_tf32(__uint_as_float(ah[3])));
#pragma unroll
                for (int ni = 0; ni < 4; ni++)
                    mma_tf32(acc[mi][ni], ah, bf[ni]);
            }
        }
        __syncthreads();
    }

    int lr = lane >> 2, lc2 = 2 * (lane & 3);
#pragma unroll
    for (int mi = 0; mi < 4; mi++) {
#pragma unroll
        for (int ni = 0; ni < 4; ni++) {
            int lcol = wn * 32 + ni * 8 + lc2;
            float b0 = bssh[lcol], b1 = bssh[lcol + 1];
            int row0 = m0 + wm * 64 + mi * 16 + lr;
            if (row0 < MM) {
                float2 o = make_float2(acc[mi][ni][0] + b0, acc[mi][ni][1] + b1);
                *(float2*)(out + (size_t)row0 * CC + n0 + lcol) = o;
            }
            int row1 = row0 + 8;
            if (row1 < MM) {
                float2 o = make_float2(acc[mi][ni][2] + b0, acc[mi][ni][3] + b1);
                *(float2*)(out + (size_t)row1 * CC + n0 + lcol) = o;
            }
        }
    }
}

// ---------------------------------------------------------------------------
__global__ void v_out_kernel(const float* __restrict__ Wv,
                             const float* __restrict__ bv,
                             float* __restrict__ out_v) {
    int i = blockIdx.x * blockDim.x + threadIdx.x;
    if (i >= MM * VCD) return;
    int m = i / 48;
    int r = i % 48;
    int o = r / 3, d = r % 3;
    const float* vm = g_v_mean + (size_t)m * 48;
    const float* w  = Wv + o * 16;
    float sum = 0.f;
#pragma unroll
    for (int c = 0; c < 16; c++) sum += w[c] * vm[c * 3 + d];
    out_v[i] = sum + bv[o];
}

// ---------------------------------------------------------------------------
extern "C" void kernel_launch(void* const* d_in, const int* in_sizes, int n_in,
                              void* d_out, int out_size) {
    const float* s   = (const float*)d_in[0];
    const float* v   = (const float*)d_in[1];
    const void*  seg = d_in[2];
    const float* Ws  = (const float*)d_in[3];
    const float* bs  = (const float*)d_in[4];
    const float* Wv  = (const float*)d_in[5];
    const float* bv  = (const float*)d_in[6];
    float* out_s = (float*)d_out;
    float* out_v = out_s + (size_t)MM * CC;

    static int smem_set = 0;
    if (!smem_set) {
        cudaFuncSetAttribute(gemm_s_mma,
                             cudaFuncAttributeMaxDynamicSharedMemorySize, SMO_TOTAL);
        smem_set = 1;
    }

    probe_seg_kernel<<<1, 256>>>((const int*)seg);
    zero_hist_kernel<<<(MM + 255) / 256, 256>>>();
    hist_kernel<<<(NN + 255) / 256, 256>>>(seg);
    scan_a_kernel<<<NB, 256>>>();
    scan_c_kernel<<<NB, 256>>>();
    perm_kernel<<<(NN + 255) / 256, 256>>>(seg);
    gather_mean_kernel<<<(MM * 32 + 255) / 256, 256>>>(s, v);

    dim3 gg(CC / 128, (MM + 127) / 128);
    gemm_s_mma<<<gg, 256, SMO_TOTAL>>>(Ws, bs, out_s);

    v_out_kernel<<<(MM * VCD + 255) / 256, 256>>>(Wv, bv, out_v);
}

// round 14
// speedup vs baseline: 1.3376x; 1.3376x over previous
#include <cuda_runtime.h>
#include <cstdint>

#define NN 200000
#define CC 256
#define MM 50000
#define VCD 48   // 16 vector channels * 3 spatial dims
#define NB 98    // scan blocks: ceil(MM / 512)

// Scratch (device globals; no allocation allowed in kernel_launch)
__device__ float g_s_mean[(size_t)MM * CC];   // 51.2 MB
__device__ float g_v_mean[(size_t)MM * VCD];  // 9.6 MB
__device__ int   g_hist[MM];
__device__ int   g_bsum[NB];
__device__ int   g_off[MM + 1];
__device__ int   g_fill[MM];
__device__ int   g_perm[NN];
__device__ int   g_seg_is64;

// ============================ helpers ======================================
__device__ __forceinline__ uint32_t smem_u32(const void* p) {
    uint32_t a;
    asm("{ .reg .u64 t; cvta.to.shared.u64 t, %1; cvt.u32.u64 %0, t; }"
        : "=r"(a) : "l"(p));
    return a;
}
__device__ __forceinline__ float to_tf32(float x) {
    float r;
    asm("cvt.rna.tf32.f32 %0, %1;" : "=f"(r) : "f"(x));
    return r;
}
__device__ __forceinline__ void ldsm_x4(uint32_t* r, uint32_t addr) {
    asm volatile("ldmatrix.sync.aligned.m8n8.x4.shared.b16 {%0,%1,%2,%3}, [%4];"
        : "=r"(r[0]), "=r"(r[1]), "=r"(r[2]), "=r"(r[3]) : "r"(addr));
}
__device__ __forceinline__ void ldsm_x2(uint32_t* r, uint32_t addr) {
    asm volatile("ldmatrix.sync.aligned.m8n8.x2.shared.b16 {%0,%1}, [%2];"
        : "=r"(r[0]), "=r"(r[1]) : "r"(addr));
}
__device__ __forceinline__ void mma_tf32(float* c, const uint32_t* a, const uint32_t* b) {
    asm volatile(
        "mma.sync.aligned.m16n8k8.row.col.f32.tf32.tf32.f32 "
        "{%0,%1,%2,%3}, {%4,%5,%6,%7}, {%8,%9}, {%0,%1,%2,%3};"
        : "+f"(c[0]), "+f"(c[1]), "+f"(c[2]), "+f"(c[3])
        : "r"(a[0]), "r"(a[1]), "r"(a[2]), "r"(a[3]), "r"(b[0]), "r"(b[1]));
}
__device__ __forceinline__ void cp_async16(uint32_t saddr, const void* gaddr,
                                           uint32_t src_size) {
    asm volatile("cp.async.ca.shared.global [%0], [%1], 16, %2;"
                 :: "r"(saddr), "l"(gaddr), "r"(src_size) : "memory");
}
__device__ __forceinline__ void add4(float4& a, const float4 b) {
    a.x += b.x; a.y += b.y; a.z += b.z; a.w += b.w;
}

// ---------------------------------------------------------------------------
// Probe the segment-index buffer's dtype (int64 vs int32).
// ---------------------------------------------------------------------------
__global__ void probe_seg_kernel(const int* __restrict__ seg32) {
    __shared__ int any_nonzero;
    if (threadIdx.x == 0) any_nonzero = 0;
    __syncthreads();
    for (int i = threadIdx.x; i < 1024; i += blockDim.x)
        if (seg32[2 * i + 1] != 0) any_nonzero = 1;
    __syncthreads();
    if (threadIdx.x == 0) g_seg_is64 = (any_nonzero == 0) ? 1 : 0;
}
__device__ __forceinline__ int load_seg(const void* seg, int n, int is64) {
    if (is64) return (int)((const long long*)seg)[n];
    return ((const int*)seg)[n];
}

// ======================= counting sort build ===============================
__global__ void zero_hist_kernel() {
    int i = blockIdx.x * blockDim.x + threadIdx.x;
    if (i < MM) g_hist[i] = 0;
}

__global__ void hist_kernel(const void* __restrict__ seg) {
    int n = blockIdx.x * blockDim.x + threadIdx.x;
    if (n >= NN) return;
    int m = load_seg(seg, n, g_seg_is64);
    if ((unsigned)m < MM) atomicAdd(&g_hist[m], 1);
}

// scan_a: per-block (512 elems) sum
__global__ void scan_a_kernel() {
    __shared__ int red[256];
    int b = blockIdx.x, t = threadIdx.x;
    int i0 = b * 512 + t, i1 = i0 + 256;
    int c = (i0 < MM ? g_hist[i0] : 0) + (i1 < MM ? g_hist[i1] : 0);
    red[t] = c;
    __syncthreads();
    for (int s = 128; s > 0; s >>= 1) {
        if (t < s) red[t] += red[t + s];
        __syncthreads();
    }
    if (t == 0) g_bsum[b] = red[0];
}

// scan_b: exclusive scan of NB block sums, total to g_off[MM]
__global__ void scan_b_kernel() {
    __shared__ int sh[NB];
    int t = threadIdx.x;
    for (int i = t; i < NB; i += blockDim.x) sh[i] = g_bsum[i];
    __syncthreads();
    if (t == 0) {
        int run = 0;
        for (int i = 0; i < NB; i++) { int tmp = sh[i]; sh[i] = run; run += tmp; }
        g_off[MM] = run;
    }
    __syncthreads();
    for (int i = t; i < NB; i += blockDim.x) g_bsum[i] = sh[i];
}

// scan_c: per-block exclusive scan + block base -> g_off, g_fill
__global__ void scan_c_kernel() {
    __shared__ int buf0[256], buf1[256];
    int b = blockIdx.x, t = threadIdx.x;
    int i0 = b * 512 + 2 * t, i1 = i0 + 1;
    int c0 = (i0 < MM) ? g_hist[i0] : 0;
    int c1 = (i1 < MM) ? g_hist[i1] : 0;
    int psum = c0 + c1;
    buf0[t] = psum;
    __syncthreads();
    int* src = buf0; int* dst = buf1;
#pragma unroll
    for (int off = 1; off < 256; off <<= 1) {
        int val = src[t];
        if (t >= off) val += src[t - off];
        dst[t] = val;
        __syncthreads();
        int* tmp = src; src = dst; dst = tmp;
    }
    int excl = src[t] - psum;
    int base = g_bsum[b] + excl;
    if (i0 < MM) { g_off[i0] = base;      g_fill[i0] = base; }
    if (i1 < MM) { g_off[i1] = base + c0; g_fill[i1] = base + c0; }
}

__global__ void perm_kernel(const void* __restrict__ seg) {
    int n = blockIdx.x * blockDim.x + threadIdx.x;
    if (n >= NN) return;
    int m = load_seg(seg, n, g_seg_is64);
    if ((unsigned)m >= MM) return;
    int pos = atomicAdd(&g_fill[m], 1);
    g_perm[pos] = n;
}

// ---------------------------------------------------------------------------
// gather_mean (R9 proven version): one warp per motif, 2-node unroll.
// ---------------------------------------------------------------------------
__global__ void __launch_bounds__(256)
gather_mean_kernel(const float* __restrict__ s, const float* __restrict__ v) {
    int w = (blockIdx.x * blockDim.x + threadIdx.x) >> 5;
    if (w >= MM) return;
    int lane = threadIdx.x & 31;
    int beg = g_off[w], end = g_off[w + 1];

    float4 a0 = make_float4(0.f, 0.f, 0.f, 0.f), a1 = a0;
    float4 b0 = a0, b1 = a0;
    float4 va = a0, vb = a0;
    const float4* s4 = (const float4*)s;
    const float4* v4 = (const float4*)v;

    int i = beg;
    for (; i + 1 < end; i += 2) {
        int n0 = g_perm[i], n1 = g_perm[i + 1];
        add4(a0, s4[(size_t)n0 * 64 + lane * 2]);
        add4(b0, s4[(size_t)n1 * 64 + lane * 2]);
        add4(a1, s4[(size_t)n0 * 64 + lane * 2 + 1]);
        add4(b1, s4[(size_t)n1 * 64 + lane * 2 + 1]);
        if (lane < 12) {
            add4(va, v4[(size_t)n0 * 12 + lane]);
            add4(vb, v4[(size_t)n1 * 12 + lane]);
        }
    }
    if (i < end) {
        int n0 = g_perm[i];
        add4(a0, s4[(size_t)n0 * 64 + lane * 2]);
        add4(a1, s4[(size_t)n0 * 64 + lane * 2 + 1]);
        if (lane < 12) add4(va, v4[(size_t)n0 * 12 + lane]);
    }
    add4(a0, b0); add4(a1, b1); add4(va, vb);

    int cnt = end - beg;
    float inv = 1.0f / (float)(cnt > 0 ? cnt : 1);
    a0.x *= inv; a0.y *= inv; a0.z *= inv; a0.w *= inv;
    a1.x *= inv; a1.y *= inv; a1.z *= inv; a1.w *= inv;
    ((float4*)g_s_mean)[(size_t)w * 64 + lane * 2]     = a0;
    ((float4*)g_s_mean)[(size_t)w * 64 + lane * 2 + 1] = a1;
    if (lane < 12) {
        va.x *= inv; va.y *= inv; va.z *= inv; va.w *= inv;
        ((float4*)g_v_mean)[(size_t)w * 12 + lane] = va;
    }
}

// ---------------------------------------------------------------------------
// Single-pass tf32 mma.sync GEMM, cp.async double-buffered A and B (raw f32
// tiles), tf32 rounding post-ldmatrix. BM=128, BN=128, BK=32, occ=2.
// ---------------------------------------------------------------------------
#define SMO_BS   0
#define SMO_A    1024                 // 2 stages x 16KB
#define SMO_B    (1024 + 32768)       // 2 stages x 16KB
#define SMO_TOTAL (1024 + 65536)

__global__ void __launch_bounds__(256, 2)
gemm_s_mma(const float* __restrict__ Ws, const float* __restrict__ bs,
           float* __restrict__ out) {
    extern __shared__ char sm[];
    uint32_t sb = smem_u32(sm);
    int tid = threadIdx.x, wid = tid >> 5, lane = tid & 31;
    int wm = wid & 1, wn = wid >> 1;
    int m0 = blockIdx.y * 128, n0 = blockIdx.x * 128;

    float* bssh = (float*)(sm + SMO_BS);
    if (tid < 128) bssh[tid] = bs[n0 + tid];

    const float* gA[4]; const float* gB[4];
    uint32_t offAB[4]; uint32_t szA[4];
#pragma unroll
    for (int i = 0; i < 4; i++) {
        int f = tid + 256 * i;
        int row = f >> 3, q = f & 7;
        int gm = m0 + row;
        bool ok = (gm < MM);
        gA[i] = g_s_mean + (size_t)(ok ? gm : 0) * CC + q * 4;
        szA[i] = ok ? 16u : 0u;
        gB[i] = Ws + (size_t)(n0 + row) * CC + q * 4;
        offAB[i] = row * 128 + ((q ^ (row & 7)) << 4);
    }

    float acc[4][4][4];
#pragma unroll
    for (int a = 0; a < 4; a++)
#pragma unroll
        for (int b = 0; b < 4; b++)
#pragma unroll
            for (int c = 0; c < 4; c++) acc[a][b][c] = 0.f;

    int r8 = lane & 7;
    int halfA = (lane >> 3) & 1;
    int ksubA = lane >> 4;
    int ksubB = (lane >> 3) & 1;
    uint32_t aRowOff[4]; int aRsw[4];
#pragma unroll
    for (int mi = 0; mi < 4; mi++) {
        int row = wm * 64 + mi * 16 + halfA * 8 + r8;
        aRowOff[mi] = row * 128;
        aRsw[mi] = row & 7;
    }
    uint32_t bRowOff[4];
#pragma unroll
    for (int ni = 0; ni < 4; ni++)
        bRowOff[ni] = (wn * 32 + ni * 8 + r8) * 128;

#define LOAD_TILES(CH, ST)                                                        \
    {                                                                             \
        uint32_t ab = sb + SMO_A + (ST) * 16384;                                  \
        uint32_t bb = sb + SMO_B + (ST) * 16384;                                  \
        int kt = (CH) * 32;                                                       \
        _Pragma("unroll")                                                         \
        for (int i = 0; i < 4; i++) cp_async16(ab + offAB[i], gA[i] + kt, szA[i]);\
        _Pragma("unroll")                                                         \
        for (int i = 0; i < 4; i++) cp_async16(bb + offAB[i], gB[i] + kt, 16u);   \
        asm volatile("cp.async.commit_group;" ::: "memory");                      \
    }

    LOAD_TILES(0, 0)

    for (int ch = 0; ch < 8; ch++) {
        if (ch < 7) {
            LOAD_TILES(ch + 1, (ch + 1) & 1)
            asm volatile("cp.async.wait_group 1;" ::: "memory");
        } else {
            asm volatile("cp.async.wait_group 0;" ::: "memory");
        }
        __syncthreads();

        uint32_t ab = sb + SMO_A + (ch & 1) * 16384;
        uint32_t bb = sb + SMO_B + (ch & 1) * 16384;
#pragma unroll
        for (int ks = 0; ks < 4; ks++) {
            int ks2 = ks * 2;
            uint32_t bf[4][2];
#pragma unroll
            for (int ni = 0; ni < 4; ni++) {
                ldsm_x2(bf[ni], bb + bRowOff[ni] + (((ks2 + ksubB) ^ r8) << 4));
                bf[ni][0] = __float_as_uint(to_tf32(__uint_as_float(bf[ni][0])));
                bf[ni][1] = __float_as_uint(to_tf32(__uint_as_float(bf[ni][1])));
            }
#pragma unroll
            for (int mi = 0; mi < 4; mi++) {
                uint32_t ah[4];
                uint32_t ca = ((uint32_t)((ks2 + ksubA) ^ aRsw[mi])) << 4;
                ldsm_x4(ah, ab + aRowOff[mi] + ca);
                ah[0] = __float_as_uint(to_tf32(__uint_as_float(ah[0])));
                ah[1] = __float_as_uint(to_tf32(__uint_as_float(ah[1])));
                ah[2] = __float_as_uint(to_tf32(__uint_as_float(ah[2])));
                ah[3] = __float_as_uint(to_tf32(__uint_as_float(ah[3])));
#pragma unroll
                for (int ni = 0; ni < 4; ni++)
                    mma_tf32(acc[mi][ni], ah, bf[ni]);
            }
        }
        __syncthreads();
    }

    int lr = lane >> 2, lc2 = 2 * (lane & 3);
#pragma unroll
    for (int mi = 0; mi < 4; mi++) {
#pragma unroll
        for (int ni = 0; ni < 4; ni++) {
            int lcol = wn * 32 + ni * 8 + lc2;
            float b0 = bssh[lcol], b1 = bssh[lcol + 1];
            int row0 = m0 + wm * 64 + mi * 16 + lr;
            if (row0 < MM) {
                float2 o = make_float2(acc[mi][ni][0] + b0, acc[mi][ni][1] + b1);
                *(float2*)(out + (size_t)row0 * CC + n0 + lcol) = o;
            }
            int row1 = row0 + 8;
            if (row1 < MM) {
                float2 o = make_float2(acc[mi][ni][2] + b0, acc[mi][ni][3] + b1);
                *(float2*)(out + (size_t)row1 * CC + n0 + lcol) = o;
            }
        }
    }
}

// ---------------------------------------------------------------------------
__global__ void v_out_kernel(const float* __restrict__ Wv,
                             const float* __restrict__ bv,
                             float* __restrict__ out_v) {
    int i = blockIdx.x * blockDim.x + threadIdx.x;
    if (i >= MM * VCD) return;
    int m = i / 48;
    int r = i % 48;
    int o = r / 3, d = r % 3;
    const float* vm = g_v_mean + (size_t)m * 48;
    const float* w  = Wv + o * 16;
    float sum = 0.f;
#pragma unroll
    for (int c = 0; c < 16; c++) sum += w[c] * vm[c * 3 + d];
    out_v[i] = sum + bv[o];
}

// ---------------------------------------------------------------------------
extern "C" void kernel_launch(void* const* d_in, const int* in_sizes, int n_in,
                              void* d_out, int out_size) {
    const float* s   = (const float*)d_in[0];
    const float* v   = (const float*)d_in[1];
    const void*  seg = d_in[2];
    const float* Ws  = (const float*)d_in[3];
    const float* bs  = (const float*)d_in[4];
    const float* Wv  = (const float*)d_in[5];
    const float* bv  = (const float*)d_in[6];
    float* out_s = (float*)d_out;
    float* out_v = out_s + (size_t)MM * CC;

    static int smem_set = 0;
    if (!smem_set) {
        cudaFuncSetAttribute(gemm_s_mma,
                             cudaFuncAttributeMaxDynamicSharedMemorySize, SMO_TOTAL);
        smem_set = 1;
    }

    probe_seg_kernel<<<1, 256>>>((const int*)seg);
    zero_hist_kernel<<<(MM + 255) / 256, 256>>>();
    hist_kernel<<<(NN + 255) / 256, 256>>>(seg);
    scan_a_kernel<<<NB, 256>>>();
    scan_b_kernel<<<1, 128>>>();
    scan_c_kernel<<<NB, 256>>>();
    perm_kernel<<<(NN + 255) / 256, 256>>>(seg);
    gather_mean_kernel<<<(MM * 32 + 255) / 256, 256>>>(s, v);

    dim3 gg(CC / 128, (MM + 127) / 128);
    gemm_s_mma<<<gg, 256, SMO_TOTAL>>>(Ws, bs, out_s);

    v_out_kernel<<<(MM * VCD + 255) / 256, 256>>>(Wv, bv, out_v);
}

// round 15
// speedup vs baseline: 1.3542x; 1.0124x over previous
#include <cuda_runtime.h>
#include <cstdint>

#define NN 200000
#define CC 256
#define MM 50000
#define VCD 48   // 16 vector channels * 3 spatial dims
#define NB 98    // scan blocks: ceil(MM / 512)

// Scratch (device globals; no allocation allowed in kernel_launch)
__device__ float g_s_mean[(size_t)MM * CC];   // 51.2 MB
__device__ float g_v_mean[(size_t)MM * VCD];  // 9.6 MB
__device__ int   g_hist[MM];
__device__ int   g_bsum[NB];
__device__ int   g_off[MM + 1];
__device__ int   g_fill[MM];
__device__ int   g_perm[NN];
__device__ int   g_seg_is64;

// ============================ helpers ======================================
__device__ __forceinline__ uint32_t smem_u32(const void* p) {
    uint32_t a;
    asm("{ .reg .u64 t; cvta.to.shared.u64 t, %1; cvt.u32.u64 %0, t; }"
        : "=r"(a) : "l"(p));
    return a;
}
__device__ __forceinline__ float to_tf32(float x) {
    float r;
    asm("cvt.rna.tf32.f32 %0, %1;" : "=f"(r) : "f"(x));
    return r;
}
__device__ __forceinline__ void ldsm_x4(uint32_t* r, uint32_t addr) {
    asm volatile("ldmatrix.sync.aligned.m8n8.x4.shared.b16 {%0,%1,%2,%3}, [%4];"
        : "=r"(r[0]), "=r"(r[1]), "=r"(r[2]), "=r"(r[3]) : "r"(addr));
}
__device__ __forceinline__ void ldsm_x2(uint32_t* r, uint32_t addr) {
    asm volatile("ldmatrix.sync.aligned.m8n8.x2.shared.b16 {%0,%1}, [%2];"
        : "=r"(r[0]), "=r"(r[1]) : "r"(addr));
}
__device__ __forceinline__ void mma_tf32(float* c, const uint32_t* a, const uint32_t* b) {
    asm volatile(
        "mma.sync.aligned.m16n8k8.row.col.f32.tf32.tf32.f32 "
        "{%0,%1,%2,%3}, {%4,%5,%6,%7}, {%8,%9}, {%0,%1,%2,%3};"
        : "+f"(c[0]), "+f"(c[1]), "+f"(c[2]), "+f"(c[3])
        : "r"(a[0]), "r"(a[1]), "r"(a[2]), "r"(a[3]), "r"(b[0]), "r"(b[1]));
}
__device__ __forceinline__ void cp_async16(uint32_t saddr, const void* gaddr,
                                           uint32_t src_size) {
    asm volatile("cp.async.ca.shared.global [%0], [%1], 16, %2;"
                 :: "r"(saddr), "l"(gaddr), "r"(src_size) : "memory");
}
__device__ __forceinline__ void add4(float4& a, const float4 b) {
    a.x += b.x; a.y += b.y; a.z += b.z; a.w += b.w;
}

__device__ __forceinline__ int load_seg(const void* seg, int n, int is64) {
    if (is64) return (int)((const long long*)seg)[n];
    return ((const int*)seg)[n];
}

// ---------------------------------------------------------------------------
// Fused: zero g_hist + probe segment dtype (block 0 only does the probe).
// ---------------------------------------------------------------------------
__global__ void probe_zero_kernel(const int* __restrict__ seg32) {
    int i = blockIdx.x * blockDim.x + threadIdx.x;
    if (i < MM) g_hist[i] = 0;
    if (blockIdx.x == 0) {
        __shared__ int any_nonzero;
        if (threadIdx.x == 0) any_nonzero = 0;
        __syncthreads();
        for (int k = threadIdx.x; k < 1024; k += blockDim.x)
            if (seg32[2 * k + 1] != 0) any_nonzero = 1;
        __syncthreads();
        if (threadIdx.x == 0) g_seg_is64 = (any_nonzero == 0) ? 1 : 0;
    }
}

// ======================= counting sort build ===============================
__global__ void hist_kernel(const void* __restrict__ seg) {
    int n = blockIdx.x * blockDim.x + threadIdx.x;
    if (n >= NN) return;
    int m = load_seg(seg, n, g_seg_is64);
    if ((unsigned)m < MM) atomicAdd(&g_hist[m], 1);
}

// scan_a: per-block (512 elems) sum
__global__ void scan_a_kernel() {
    __shared__ int red[256];
    int b = blockIdx.x, t = threadIdx.x;
    int i0 = b * 512 + t, i1 = i0 + 256;
    int c = (i0 < MM ? g_hist[i0] : 0) + (i1 < MM ? g_hist[i1] : 0);
    red[t] = c;
    __syncthreads();
    for (int s = 128; s > 0; s >>= 1) {
        if (t < s) red[t] += red[t + s];
        __syncthreads();
    }
    if (t == 0) g_bsum[b] = red[0];
}

// scan_c: per-block exclusive scan over its 512 counts; the 98-block-sum
// prefix is computed locally from raw g_bsum (scan_b eliminated). Block 0
// also writes the grand total to g_off[MM].
__global__ void scan_c_kernel() {
    __shared__ int buf0[256], buf1[256];
    __shared__ int bs_sh[NB];
    __shared__ int base_blk;
    int b = blockIdx.x, t = threadIdx.x;
    for (int i = t; i < NB; i += blockDim.x) bs_sh[i] = g_bsum[i];

    int i0 = b * 512 + 2 * t, i1 = i0 + 1;
    int c0 = (i0 < MM) ? g_hist[i0] : 0;
    int c1 = (i1 < MM) ? g_hist[i1] : 0;
    int psum = c0 + c1;
    buf0[t] = psum;
    __syncthreads();

    if (t == 0) {
        int run = 0;
        for (int i = 0; i < b; i++) run += bs_sh[i];
        base_blk = run;
        if (b == 0) {
            int tot = 0;
            for (int i = 0; i < NB; i++) tot += bs_sh[i];
            g_off[MM] = tot;
        }
    }

    int* src = buf0; int* dst = buf1;
#pragma unroll
    for (int off = 1; off < 256; off <<= 1) {
        int val = src[t];
        if (t >= off) val += src[t - off];
        dst[t] = val;
        __syncthreads();
        int* tmp = src; src = dst; dst = tmp;
    }
    int excl = src[t] - psum;
    int base = base_blk + excl;
    if (i0 < MM) { g_off[i0] = base;      g_fill[i0] = base; }
    if (i1 < MM) { g_off[i1] = base + c0; g_fill[i1] = base + c0; }
}

__global__ void perm_kernel(const void* __restrict__ seg) {
    int n = blockIdx.x * blockDim.x + threadIdx.x;
    if (n >= NN) return;
    int m = load_seg(seg, n, g_seg_is64);
    if ((unsigned)m >= MM) return;
    int pos = atomicAdd(&g_fill[m], 1);
    g_perm[pos] = n;
}

// ---------------------------------------------------------------------------
// gather_mean (R9/R11 proven): one warp per motif, 2-node unroll.
// ---------------------------------------------------------------------------
__global__ void __launch_bounds__(256)
gather_mean_kernel(const float* __restrict__ s, const float* __restrict__ v) {
    int w = (blockIdx.x * blockDim.x + threadIdx.x) >> 5;
    if (w >= MM) return;
    int lane = threadIdx.x & 31;
    int beg = g_off[w], end = g_off[w + 1];

    float4 a0 = make_float4(0.f, 0.f, 0.f, 0.f), a1 = a0;
    float4 b0 = a0, b1 = a0;
    float4 va = a0, vb = a0;
    const float4* s4 = (const float4*)s;
    const float4* v4 = (const float4*)v;

    int i = beg;
    for (; i + 1 < end; i += 2) {
        int n0 = g_perm[i], n1 = g_perm[i + 1];
        add4(a0, s4[(size_t)n0 * 64 + lane * 2]);
        add4(b0, s4[(size_t)n1 * 64 + lane * 2]);
        add4(a1, s4[(size_t)n0 * 64 + lane * 2 + 1]);
        add4(b1, s4[(size_t)n1 * 64 + lane * 2 + 1]);
        if (lane < 12) {
            add4(va, v4[(size_t)n0 * 12 + lane]);
            add4(vb, v4[(size_t)n1 * 12 + lane]);
        }
    }
    if (i < end) {
        int n0 = g_perm[i];
        add4(a0, s4[(size_t)n0 * 64 + lane * 2]);
        add4(a1, s4[(size_t)n0 * 64 + lane * 2 + 1]);
        if (lane < 12) add4(va, v4[(size_t)n0 * 12 + lane]);
    }
    add4(a0, b0); add4(a1, b1); add4(va, vb);

    int cnt = end - beg;
    float inv = 1.0f / (float)(cnt > 0 ? cnt : 1);
    a0.x *= inv; a0.y *= inv; a0.z *= inv; a0.w *= inv;
    a1.x *= inv; a1.y *= inv; a1.z *= inv; a1.w *= inv;
    ((float4*)g_s_mean)[(size_t)w * 64 + lane * 2]     = a0;
    ((float4*)g_s_mean)[(size_t)w * 64 + lane * 2 + 1] = a1;
    if (lane < 12) {
        va.x *= inv; va.y *= inv; va.z *= inv; va.w *= inv;
        ((float4*)g_v_mean)[(size_t)w * 12 + lane] = va;
    }
}

// ---------------------------------------------------------------------------
// Single-pass tf32 mma.sync GEMM, cp.async double-buffered A and B (raw f32
// tiles), tf32 rounding post-ldmatrix. BM=128, BN=128, BK=32, occ=2.
// (R11/R14 proven version, unchanged.)
// ---------------------------------------------------------------------------
#define SMO_BS   0
#define SMO_A    1024                 // 2 stages x 16KB
#define SMO_B    (1024 + 32768)       // 2 stages x 16KB
#define SMO_TOTAL (1024 + 65536)

__global__ void __launch_bounds__(256, 2)
gemm_s_mma(const float* __restrict__ Ws, const float* __restrict__ bs,
           float* __restrict__ out) {
    extern __shared__ char sm[];
    uint32_t sb = smem_u32(sm);
    int tid = threadIdx.x, wid = tid >> 5, lane = tid & 31;
    int wm = wid & 1, wn = wid >> 1;
    int m0 = blockIdx.y * 128, n0 = blockIdx.x * 128;

    float* bssh = (float*)(sm + SMO_BS);
    if (tid < 128) bssh[tid] = bs[n0 + tid];

    const float* gA[4]; const float* gB[4];
    uint32_t offAB[4]; uint32_t szA[4];
#pragma unroll
    for (int i = 0; i < 4; i++) {
        int f = tid + 256 * i;
        int row = f >> 3, q = f & 7;
        int gm = m0 + row;
        bool ok = (gm < MM);
        gA[i] = g_s_mean + (size_t)(ok ? gm : 0) * CC + q * 4;
        szA[i] = ok ? 16u : 0u;
        gB[i] = Ws + (size_t)(n0 + row) * CC + q * 4;
        offAB[i] = row * 128 + ((q ^ (row & 7)) << 4);
    }

    float acc[4][4][4];
#pragma unroll
    for (int a = 0; a < 4; a++)
#pragma unroll
        for (int b = 0; b < 4; b++)
#pragma unroll
            for (int c = 0; c < 4; c++) acc[a][b][c] = 0.f;

    int r8 = lane & 7;
    int halfA = (lane >> 3) & 1;
    int ksubA = lane >> 4;
    int ksubB = (lane >> 3) & 1;
    uint32_t aRowOff[4]; int aRsw[4];
#pragma unroll
    for (int mi = 0; mi < 4; mi++) {
        int row = wm * 64 + mi * 16 + halfA * 8 + r8;
        aRowOff[mi] = row * 128;
        aRsw[mi] = row & 7;
    }
    uint32_t bRowOff[4];
#pragma unroll
    for (int ni = 0; ni < 4; ni++)
        bRowOff[ni] = (wn * 32 + ni * 8 + r8) * 128;

#define LOAD_TILES(CH, ST)                                                        \
    {                                                                             \
        uint32_t ab = sb + SMO_A + (ST) * 16384;                                  \
        uint32_t bb = sb + SMO_B + (ST) * 16384;                                  \
        int kt = (CH) * 32;                                                       \
        _Pragma("unroll")                                                         \
        for (int i = 0; i < 4; i++) cp_async16(ab + offAB[i], gA[i] + kt, szA[i]);\
        _Pragma("unroll")                                                         \
        for (int i = 0; i < 4; i++) cp_async16(bb + offAB[i], gB[i] + kt, 16u);   \
        asm volatile("cp.async.commit_group;" ::: "memory");                      \
    }

    LOAD_TILES(0, 0)

    for (int ch = 0; ch < 8; ch++) {
        if (ch < 7) {
            LOAD_TILES(ch + 1, (ch + 1) & 1)
            asm volatile("cp.async.wait_group 1;" ::: "memory");
        } else {
            asm volatile("cp.async.wait_group 0;" ::: "memory");
        }
        __syncthreads();

        uint32_t ab = sb + SMO_A + (ch & 1) * 16384;
        uint32_t bb = sb + SMO_B + (ch & 1) * 16384;
#pragma unroll
        for (int ks = 0; ks < 4; ks++) {
            int ks2 = ks * 2;
            uint32_t bf[4][2];
#pragma unroll
            for (int ni = 0; ni < 4; ni++) {
                ldsm_x2(bf[ni], bb + bRowOff[ni] + (((ks2 + ksubB) ^ r8) << 4));
                bf[ni][0] = __float_as_uint(to_tf32(__uint_as_float(bf[ni][0])));
                bf[ni][1] = __float_as_uint(to_tf32(__uint_as_float(bf[ni][1])));
            }
#pragma unroll
            for (int mi = 0; mi < 4; mi++) {
                uint32_t ah[4];
                uint32_t ca = ((uint32_t)((ks2 + ksubA) ^ aRsw[mi])) << 4;
                ldsm_x4(ah, ab + aRowOff[mi] + ca);
                ah[0] = __float_as_uint(to_tf32(__uint_as_float(ah[0])));
                ah[1] = __float_as_uint(to_tf32(__uint_as_float(ah[1])));
                ah[2] = __float_as_uint(to_tf32(__uint_as_float(ah[2])));
                ah[3] = __float_as_uint(to_tf32(__uint_as_float(ah[3])));
#pragma unroll
                for (int ni = 0; ni < 4; ni++)
                    mma_tf32(acc[mi][ni], ah, bf[ni]);
            }
        }
        __syncthreads();
    }

    int lr = lane >> 2, lc2 = 2 * (lane & 3);
#pragma unroll
    for (int mi = 0; mi < 4; mi++) {
#pragma unroll
        for (int ni = 0; ni < 4; ni++) {
            int lcol = wn * 32 + ni * 8 + lc2;
            float b0 = bssh[lcol], b1 = bssh[lcol + 1];
            int row0 = m0 + wm * 64 + mi * 16 + lr;
            if (row0 < MM) {
                float2 o = make_float2(acc[mi][ni][0] + b0, acc[mi][ni][1] + b1);
                *(float2*)(out + (size_t)row0 * CC + n0 + lcol) = o;
            }
            int row1 = row0 + 8;
            if (row1 < MM) {
                float2 o = make_float2(acc[mi][ni][2] + b0, acc[mi][ni][3] + b1);
                *(float2*)(out + (size_t)row1 * CC + n0 + lcol) = o;
            }
        }
    }
}

// ---------------------------------------------------------------------------
__global__ void v_out_kernel(const float* __restrict__ Wv,
                             const float* __restrict__ bv,
                             float* __restrict__ out_v) {
    int i = blockIdx.x * blockDim.x + threadIdx.x;
    if (i >= MM * VCD) return;
    int m = i / 48;
    int r = i % 48;
    int o = r / 3, d = r % 3;
    const float* vm = g_v_mean + (size_t)m * 48;
    const float* w  = Wv + o * 16;
    float sum = 0.f;
#pragma unroll
    for (int c = 0; c < 16; c++) sum += w[c] * vm[c * 3 + d];
    out_v[i] = sum + bv[o];
}

// ---------------------------------------------------------------------------
extern "C" void kernel_launch(void* const* d_in, const int* in_sizes, int n_in,
                              void* d_out, int out_size) {
    const float* s   = (const float*)d_in[0];
    const float* v   = (const float*)d_in[1];
    const void*  seg = d_in[2];
    const float* Ws  = (const float*)d_in[3];
    const float* bs  = (const float*)d_in[4];
    const float* Wv  = (const float*)d_in[5];
    const float* bv  = (const float*)d_in[6];
    float* out_s = (float*)d_out;
    float* out_v = out_s + (size_t)MM * CC;

    static int smem_set = 0;
    if (!smem_set) {
        cudaFuncSetAttribute(gemm_s_mma,
                             cudaFuncAttributeMaxDynamicSharedMemorySize, SMO_TOTAL);
        smem_set = 1;
    }

    probe_zero_kernel<<<(MM + 255) / 256, 256>>>((const int*)seg);
    hist_kernel<<<(NN + 255) / 256, 256>>>(seg);
    scan_a_kernel<<<NB, 256>>>();
    scan_c_kernel<<<NB, 256>>>();
    perm_kernel<<<(NN + 255) / 256, 256>>>(seg);
    gather_mean_kernel<<<(MM * 32 + 255) / 256, 256>>>(s, v);   // launch #6 -> profiled

    dim3 gg(CC / 128, (MM + 127) / 128);
    gemm_s_mma<<<gg, 256, SMO_TOTAL>>>(Ws, bs, out_s);

    v_out_kernel<<<(MM * VCD + 255) / 256, 256>>>(Wv, bv, out_v);
}